// round 7
// baseline (speedup 1.0000x reference)
#include <cuda_runtime.h>
#include <cuda_fp16.h>
#include <cstdint>

#define BATCH   128
#define IN_DIM  1024
#define OUT_DIM 1024
#define ZD      128

#define NO_     4                    // o-values per CTA (main kernel)
#define ISPLIT  2                    // i-range splits
#define I_PER   (IN_DIM / ISPLIT)    // 512
#define ITERS   (I_PER / 8)          // 64
#define ROWH2   68                   // smem row stride in half2 words (64 + 4 pad)

// ---------------- helpers ----------------
__device__ __forceinline__ void mma_fp16(float* c, const uint32_t* a,
                                         uint32_t b0, uint32_t b1) {
    asm volatile(
        "mma.sync.aligned.m16n8k16.row.col.f32.f16.f16.f32 "
        "{%0,%1,%2,%3},{%4,%5,%6,%7},{%8,%9},{%0,%1,%2,%3};"
        : "+f"(c[0]), "+f"(c[1]), "+f"(c[2]), "+f"(c[3])
        : "r"(a[0]), "r"(a[1]), "r"(a[2]), "r"(a[3]), "r"(b0), "r"(b1));
}

__device__ __forceinline__ uint32_t f2h2(float lo, float hi) {
    __half2 h = __float22half2_rn(make_float2(lo, hi));
    return *(uint32_t*)&h;
}

// ---------------- K_init: out = bb + dbb + z @ dbW^T (tiled, full overwrite) ----------------
__global__ void __launch_bounds__(256)
k_init(const float* __restrict__ z, const float* __restrict__ dbW,
       const float* __restrict__ bb, const float* __restrict__ dbb,
       float* __restrict__ out) {
    __shared__ float zs[128][36];
    __shared__ float wsm[32][36];
    const int t  = threadIdx.x;
    const int o0 = blockIdx.x * 32;   // 32 o-tiles
    const int ty = t >> 3;            // 0..31 -> batch quad
    const int tx = t & 7;             // 0..7  -> o quad
    float acc[4][4] = {};
    for (int it = 0; it < ZD; it += 32) {
        {   // stage z tile: 128 rows x 32 cols
            int r = t >> 1;
            int c = (t & 1) * 16;
            const float4* src = (const float4*)(z + (size_t)r * ZD + it + c);
#pragma unroll
            for (int q = 0; q < 4; q++)
                *(float4*)&zs[r][c + 4 * q] = src[q];
        }
        {   // stage dbW tile: 32 rows x 32 cols
            int r = t >> 3;
            int c = (t & 7) * 4;
            *(float4*)&wsm[r][c] = *(const float4*)(dbW + (size_t)(o0 + r) * ZD + it + c);
        }
        __syncthreads();
#pragma unroll 8
        for (int j = 0; j < 32; j++) {
            float zr[4], wr[4];
#pragma unroll
            for (int q = 0; q < 4; q++) zr[q] = zs[ty * 4 + q][j];
#pragma unroll
            for (int q = 0; q < 4; q++) wr[q] = wsm[tx * 4 + q][j];
#pragma unroll
            for (int p = 0; p < 4; p++)
#pragma unroll
                for (int q = 0; q < 4; q++)
                    acc[p][q] += zr[p] * wr[q];
        }
        __syncthreads();
    }
#pragma unroll
    for (int p = 0; p < 4; p++)
#pragma unroll
        for (int q = 0; q < 4; q++) {
            int o = o0 + tx * 4 + q;
            out[(size_t)(ty * 4 + p) * OUT_DIM + o] = acc[p][q] + bb[o] + dbb[o];
        }
}

// ---------------- K_base: out += x @ (base_weight + dw_b)^T  (fp32 tiled, atomic i-splits) ----------------
__global__ void __launch_bounds__(256)
k_base(const float* __restrict__ x, const float* __restrict__ bw,
       const float* __restrict__ dwb, float* __restrict__ out) {
    __shared__ float xs[128][36];
    __shared__ float wsm[32][36];
    const int t  = threadIdx.x;
    const int o0 = blockIdx.x * 32;   // 32 o-tiles
    const int ib = blockIdx.y * 128;  // 8 i-splits
    const int ty = t >> 3;
    const int tx = t & 7;
    float acc[4][4] = {};
    for (int it = 0; it < 128; it += 32) {
        {
            int r = t >> 1;
            int c = (t & 1) * 16;
            const float4* src = (const float4*)(x + (size_t)r * IN_DIM + ib + it + c);
#pragma unroll
            for (int q = 0; q < 4; q++)
                *(float4*)&xs[r][c + 4 * q] = src[q];
        }
        {
            int r = t >> 3;
            int c = (t & 7) * 4;
            size_t off = (size_t)(o0 + r) * IN_DIM + ib + it + c;
            float4 a = *(const float4*)(bw + off);
            float4 b = *(const float4*)(dwb + off);
            *(float4*)&wsm[r][c] = make_float4(a.x + b.x, a.y + b.y, a.z + b.z, a.w + b.w);
        }
        __syncthreads();
#pragma unroll 8
        for (int j = 0; j < 32; j++) {
            float xr[4], wr[4];
#pragma unroll
            for (int q = 0; q < 4; q++) xr[q] = xs[ty * 4 + q][j];
#pragma unroll
            for (int q = 0; q < 4; q++) wr[q] = wsm[tx * 4 + q][j];
#pragma unroll
            for (int p = 0; p < 4; p++)
#pragma unroll
                for (int q = 0; q < 4; q++)
                    acc[p][q] += xr[p] * wr[q];
        }
        __syncthreads();
    }
#pragma unroll
    for (int p = 0; p < 4; p++)
#pragma unroll
        for (int q = 0; q < 4; q++)
            atomicAdd(&out[(size_t)(ty * 4 + p) * OUT_DIM + o0 + tx * 4 + q], acc[p][q]);
}

// ---------------- K_main: z-stationary fp16 mma.sync m16n8k16 ----------------
// out[b, o] += sum_i x[b,i] * ( sum_k dwW[(o*IN+i), k] * z[b,k] )
__global__ void __launch_bounds__(256, 2)
k_main(const float* __restrict__ x, const float* __restrict__ z,
       const float* __restrict__ dwW, float* __restrict__ out) {
    // [buf][row: o'*8+i'][half2 words]; stride 68 words == 4 (mod 32) -> LDS bank 4g+tig
    __shared__ __align__(16) __half2 ws[2][NO_ * 8][ROWH2];

    const int tid  = threadIdx.x;
    const int w    = tid >> 5;
    const int lane = tid & 31;
    const int g    = lane >> 2;   // groupID
    const int tig  = lane & 3;    // threadID in group
    const int o0   = blockIdx.x * NO_;
    const int ibase = blockIdx.y * I_PER;
    const int b0r = w * 16 + g;
    const int b1r = b0r + 8;

    // --- z A-fragments (m16n8k16): loop-invariant, register-resident fp16 ---
    uint32_t zA[8][4];
    {
        const float* z0 = z + (size_t)b0r * ZD;
        const float* z1 = z + (size_t)b1r * ZD;
#pragma unroll
        for (int kb = 0; kb < 8; kb++) {
            int c = kb * 16 + 2 * tig;
            zA[kb][0] = f2h2(z0[c],     z0[c + 1]);
            zA[kb][1] = f2h2(z1[c],     z1[c + 1]);
            zA[kb][2] = f2h2(z0[c + 8], z0[c + 9]);
            zA[kb][3] = f2h2(z1[c + 8], z1[c + 9]);
        }
    }

    // --- W staging: thread owns (row r = o'*8+i', 16-float chunk c) ---
    const int sr = tid >> 3;            // 0..31
    const int sc = tid & 7;             // 0..7
    const float4* tsrc = (const float4*)(dwW
        + ((size_t)(o0 + (sr >> 3)) * IN_DIM + ibase + (sr & 7)) * ZD + sc * 16);
    // per-iter advance: 8 i-rows -> 8*ZD floats = 256 float4

    float4 pre[4];
    // prologue: load+convert+store tile 0
#pragma unroll
    for (int q = 0; q < 4; q++) pre[q] = __ldg(tsrc + q);
    {
        uint32_t* d = (uint32_t*)&ws[0][sr][sc * 8];
        *(uint4*)(d)     = make_uint4(f2h2(pre[0].x, pre[0].y), f2h2(pre[0].z, pre[0].w),
                                      f2h2(pre[1].x, pre[1].y), f2h2(pre[1].z, pre[1].w));
        *(uint4*)(d + 4) = make_uint4(f2h2(pre[2].x, pre[2].y), f2h2(pre[2].z, pre[2].w),
                                      f2h2(pre[3].x, pre[3].y), f2h2(pre[3].z, pre[3].w));
    }

    float pout[NO_][2];
#pragma unroll
    for (int o = 0; o < NO_; o++) { pout[o][0] = 0.f; pout[o][1] = 0.f; }

    const float* xp0 = x + (size_t)b0r * IN_DIM + ibase + 2 * tig;
    const float* xp1 = x + (size_t)b1r * IN_DIM + ibase + 2 * tig;

#pragma unroll 1
    for (int it = 0; it < ITERS; ++it) {
        if (it + 1 < ITERS) {
            const float4* p = tsrc + (size_t)(it + 1) * 256;
#pragma unroll
            for (int q = 0; q < 4; q++) pre[q] = __ldg(p + q);
        }
        __syncthreads();   // current buffer staged; prev buffer fully consumed

        const int buf = it & 1;
        float c[NO_][4];
#pragma unroll
        for (int o = 0; o < NO_; o++)
            c[o][0] = c[o][1] = c[o][2] = c[o][3] = 0.f;

#pragma unroll
        for (int kb = 0; kb < 8; kb++) {
#pragma unroll
            for (int o = 0; o < NO_; o++) {
                const uint32_t* row = (const uint32_t*)&ws[buf][o * 8 + g][0];
                uint32_t b0 = row[kb * 8 + tig];
                uint32_t b1 = row[kb * 8 + tig + 4];
                mma_fp16(c[o], zA[kb], b0, b1);
            }
        }

        // epilogue: contract 8 i-columns against x (fp32)
        float2 xa = *(const float2*)(xp0 + it * 8);
        float2 xb = *(const float2*)(xp1 + it * 8);
#pragma unroll
        for (int o = 0; o < NO_; o++) {
            pout[o][0] += c[o][0] * xa.x + c[o][1] * xa.y;
            pout[o][1] += c[o][2] * xb.x + c[o][3] * xb.y;
        }

        // stage next buffer from prefetch registers
        if (it + 1 < ITERS) {
            uint32_t* d = (uint32_t*)&ws[buf ^ 1][sr][sc * 8];
            *(uint4*)(d)     = make_uint4(f2h2(pre[0].x, pre[0].y), f2h2(pre[0].z, pre[0].w),
                                          f2h2(pre[1].x, pre[1].y), f2h2(pre[1].z, pre[1].w));
            *(uint4*)(d + 4) = make_uint4(f2h2(pre[2].x, pre[2].y), f2h2(pre[2].z, pre[2].w),
                                          f2h2(pre[3].x, pre[3].y), f2h2(pre[3].z, pre[3].w));
        }
    }

    // --- reduce over tig (4 lanes hold disjoint i-partials) and accumulate ---
#pragma unroll
    for (int o = 0; o < NO_; o++) {
        float v0 = pout[o][0];
        float v1 = pout[o][1];
        v0 += __shfl_xor_sync(0xffffffffu, v0, 1);
        v0 += __shfl_xor_sync(0xffffffffu, v0, 2);
        v1 += __shfl_xor_sync(0xffffffffu, v1, 1);
        v1 += __shfl_xor_sync(0xffffffffu, v1, 2);
        if (tig == 0) {
            atomicAdd(&out[(size_t)b0r * OUT_DIM + o0 + o], v0);
            atomicAdd(&out[(size_t)b1r * OUT_DIM + o0 + o], v1);
        }
    }
}

// ---------------- launch ----------------
extern "C" void kernel_launch(void* const* d_in, const int* in_sizes, int n_in,
                              void* d_out, int out_size) {
    const float* x   = (const float*)d_in[0];
    const float* z   = (const float*)d_in[1];
    const float* bw  = (const float*)d_in[2];
    const float* dwW = (const float*)d_in[3];
    const float* dwb = (const float*)d_in[4];
    const float* bb  = (const float*)d_in[5];
    const float* dbW = (const float*)d_in[6];
    const float* dbb = (const float*)d_in[7];
    float* out = (float*)d_out;

    // 1) overwrite out with all bias terms (bb + dbb + z @ dbW^T)
    k_init<<<OUT_DIM / 32, 256>>>(z, dbW, bb, dbb, out);
    // 2) += x @ (base_weight + dw_b)^T
    k_base<<<dim3(OUT_DIM / 32, 8), 256>>>(x, bw, dwb, out);
    // 3) += hyper-GEMM main term (fp16 tensor cores)
    k_main<<<dim3(OUT_DIM / NO_, ISPLIT), 256>>>(x, z, dwW, out);
}

// round 13
// speedup vs baseline: 1.4904x; 1.4904x over previous
#include <cuda_runtime.h>
#include <cuda_fp16.h>
#include <cstdint>

#define BATCH   128
#define IN_DIM  1024
#define OUT_DIM 1024
#define ZD      128

#define NO_     4                    // o-values per CTA (k_main)
#define ISPLIT  2                    // i-range splits
#define I_PER   (IN_DIM / ISPLIT)    // 512
#define ITERS   (I_PER / 8)          // 64
#define ROWW    72                   // smem row stride in 32-bit words (64 data + 8 pad)

// ---------------- helpers ----------------
__device__ __forceinline__ void mma_fp16(float* c, const uint32_t* a,
                                         uint32_t b0, uint32_t b1) {
    asm volatile(
        "mma.sync.aligned.m16n8k16.row.col.f32.f16.f16.f32 "
        "{%0,%1,%2,%3},{%4,%5,%6,%7},{%8,%9},{%0,%1,%2,%3};"
        : "+f"(c[0]), "+f"(c[1]), "+f"(c[2]), "+f"(c[3])
        : "r"(a[0]), "r"(a[1]), "r"(a[2]), "r"(a[3]), "r"(b0), "r"(b1));
}

__device__ __forceinline__ uint32_t f2h2(float lo, float hi) {
    __half2 h = __float22half2_rn(make_float2(lo, hi));
    return *(uint32_t*)&h;
}

// ---------------- k_pre: out = bb + dbb + z@dbW^T + x@(bw+dwb)^T (full overwrite) ----------------
// Concatenated-K tiled GEMM: K = 128 (z vs dbW) + 1024 (x vs bw+dwb) = 36 k-tiles of 32.
__global__ void __launch_bounds__(256)
k_pre(const float* __restrict__ x, const float* __restrict__ z,
      const float* __restrict__ bw, const float* __restrict__ dwb,
      const float* __restrict__ bb, const float* __restrict__ dbW,
      const float* __restrict__ dbb, float* __restrict__ out) {
    __shared__ float as_[32][36];   // stride 36 floats = 144 B (16B multiple)
    __shared__ float wsm[32][36];
    const int t  = threadIdx.x;
    const int o0 = blockIdx.x * 32;
    const int b0 = blockIdx.y * 32;
    const int ty = t >> 4;   // 0..15 -> 2 batch rows
    const int tx = t & 15;   // 0..15 -> 2 o cols
    const int lr = t >> 3;   // stage row 0..31
    const int lc = (t & 7) * 4;
    float acc[2][2] = {};
    for (int kt = 0; kt < 36; kt++) {
        float4 av, wv;
        if (kt < 4) {
            av = *(const float4*)(z   + (size_t)(b0 + lr) * ZD + kt * 32 + lc);
            wv = *(const float4*)(dbW + (size_t)(o0 + lr) * ZD + kt * 32 + lc);
        } else {
            av = *(const float4*)(x + (size_t)(b0 + lr) * IN_DIM + (kt - 4) * 32 + lc);
            size_t off = (size_t)(o0 + lr) * IN_DIM + (kt - 4) * 32 + lc;
            float4 a = *(const float4*)(bw + off);
            float4 d = *(const float4*)(dwb + off);
            wv = make_float4(a.x + d.x, a.y + d.y, a.z + d.z, a.w + d.w);
        }
        __syncthreads();
        *(float4*)&as_[lr][lc] = av;
        *(float4*)&wsm[lr][lc] = wv;
        __syncthreads();
#pragma unroll 8
        for (int j = 0; j < 32; j++) {
            float a0 = as_[ty * 2][j],     a1 = as_[ty * 2 + 1][j];
            float w0 = wsm[tx * 2][j],     w1 = wsm[tx * 2 + 1][j];
            acc[0][0] += a0 * w0;  acc[0][1] += a0 * w1;
            acc[1][0] += a1 * w0;  acc[1][1] += a1 * w1;
        }
    }
#pragma unroll
    for (int p = 0; p < 2; p++)
#pragma unroll
        for (int q = 0; q < 2; q++) {
            int o = o0 + tx * 2 + q;
            out[(size_t)(b0 + ty * 2 + p) * OUT_DIM + o] = acc[p][q] + bb[o] + dbb[o];
        }
}

// ---------------- k_main: z-stationary fp16 mma, distance-2 pipeline ----------------
// out[b, o] += sum_i x[b,i] * ( sum_k dwW[(o*IN+i), k] * z[b,k] )
__global__ void __launch_bounds__(256, 2)
k_main(const float* __restrict__ x, const float* __restrict__ z,
       const float* __restrict__ dwW, float* __restrict__ out) {
    // [buf][row: o'*8+i'][ROWW words]; pair-permuted: word kb*8+2*tig = b0, +1 = b1
    __shared__ __align__(16) uint32_t ws[2][NO_ * 8][ROWW];

    const int tid  = threadIdx.x;
    const int w    = tid >> 5;
    const int lane = tid & 31;
    const int g    = lane >> 2;   // groupID
    const int tig  = lane & 3;    // threadID in group
    const int o0   = blockIdx.x * NO_;
    const int ibase = blockIdx.y * I_PER;
    const int b0r = w * 16 + g;
    const int b1r = b0r + 8;

    // --- z A-fragments (m16n8k16): loop-invariant, register-resident fp16 ---
    uint32_t zA[8][4];
    {
        const float* z0 = z + (size_t)b0r * ZD;
        const float* z1 = z + (size_t)b1r * ZD;
#pragma unroll
        for (int kb = 0; kb < 8; kb++) {
            int c = kb * 16 + 2 * tig;
            zA[kb][0] = f2h2(z0[c],     z0[c + 1]);
            zA[kb][1] = f2h2(z1[c],     z1[c + 1]);
            zA[kb][2] = f2h2(z0[c + 8], z0[c + 9]);
            zA[kb][3] = f2h2(z1[c + 8], z1[c + 9]);
        }
    }

    // --- staging: thread owns (row sr = o'*8+i', kb group sc): 16 consecutive floats ---
    const int sr = tid >> 3;            // 0..31
    const int sc = tid & 7;             // 0..7 (kb group)
    const float4* tsrc = (const float4*)(dwW
        + ((size_t)(o0 + (sr >> 3)) * IN_DIM + ibase + (sr & 7)) * ZD + sc * 16);
    uint32_t* sdst = &ws[0][0][0] + sr * ROWW + sc * 8;   // buf 0 base; buf 1 = +32*ROWW

    float4 pre[4];

    // pair-permuted pack+store of pre[] into buffer bsel
#define STS_TILE(bsel)                                                         \
    do {                                                                       \
        uint32_t* d = sdst + (bsel) * (NO_ * 8 * ROWW);                        \
        *(uint4*)(d)     = make_uint4(f2h2(pre[0].x, pre[0].y),                \
                                      f2h2(pre[2].x, pre[2].y),                \
                                      f2h2(pre[0].z, pre[0].w),                \
                                      f2h2(pre[2].z, pre[2].w));               \
        *(uint4*)(d + 4) = make_uint4(f2h2(pre[1].x, pre[1].y),                \
                                      f2h2(pre[3].x, pre[3].y),                \
                                      f2h2(pre[1].z, pre[1].w),                \
                                      f2h2(pre[3].z, pre[3].w));               \
    } while (0)

    // prologue: T0 -> buf0, T1 -> pre
#pragma unroll
    for (int q = 0; q < 4; q++) pre[q] = __ldg(tsrc + q);
    STS_TILE(0);
#pragma unroll
    for (int q = 0; q < 4; q++) pre[q] = __ldg(tsrc + 256 + q);
    __syncthreads();

    float pout[NO_][2];
#pragma unroll
    for (int o = 0; o < NO_; o++) { pout[o][0] = 0.f; pout[o][1] = 0.f; }

    const float* xp0 = x + (size_t)b0r * IN_DIM + ibase + 2 * tig;
    const float* xp1 = x + (size_t)b1r * IN_DIM + ibase + 2 * tig;

#pragma unroll 1
    for (int it = 0; it < ITERS; ++it) {
        // 1) stage T_{it+1} from pre (loaded last iter / prologue)
        if (it + 1 < ITERS) STS_TILE((it + 1) & 1);
        // 2) prefetch T_{it+2}: a full iteration to land
        if (it + 2 < ITERS) {
            const float4* p = tsrc + (size_t)(it + 2) * 256;
#pragma unroll
            for (int q = 0; q < 4; q++) pre[q] = __ldg(p + q);
        }

        // 3) compute T_it
        const uint32_t* rb = &ws[it & 1][0][0];
        float c[NO_][4];
#pragma unroll
        for (int o = 0; o < NO_; o++)
            c[o][0] = c[o][1] = c[o][2] = c[o][3] = 0.f;
#pragma unroll
        for (int kb = 0; kb < 8; kb++) {
#pragma unroll
            for (int o = 0; o < NO_; o++) {
                uint2 bf = *(const uint2*)(rb + (o * 8 + g) * ROWW + kb * 8 + 2 * tig);
                mma_fp16(c[o], zA[kb], bf.x, bf.y);
            }
        }

        // 4) epilogue: contract 8 i-columns against x (fp32)
        float2 xa = *(const float2*)(xp0 + it * 8);
        float2 xb = *(const float2*)(xp1 + it * 8);
#pragma unroll
        for (int o = 0; o < NO_; o++) {
            pout[o][0] += c[o][0] * xa.x + c[o][1] * xa.y;
            pout[o][1] += c[o][2] * xb.x + c[o][3] * xb.y;
        }

        // 5) single barrier: separates this iter's reads of buf (it&1) from
        //    next iter's STS into buf (it&1), and makes STS_TILE visible.
        __syncthreads();
    }
#undef STS_TILE

    // --- reduce over tig (4 lanes hold disjoint i-partials) and accumulate ---
#pragma unroll
    for (int o = 0; o < NO_; o++) {
        float v0 = pout[o][0];
        float v1 = pout[o][1];
        v0 += __shfl_xor_sync(0xffffffffu, v0, 1);
        v0 += __shfl_xor_sync(0xffffffffu, v0, 2);
        v1 += __shfl_xor_sync(0xffffffffu, v1, 1);
        v1 += __shfl_xor_sync(0xffffffffu, v1, 2);
        if (tig == 0) {
            atomicAdd(&out[(size_t)b0r * OUT_DIM + o0 + o], v0);
            atomicAdd(&out[(size_t)b1r * OUT_DIM + o0 + o], v1);
        }
    }
}

// ---------------- launch ----------------
extern "C" void kernel_launch(void* const* d_in, const int* in_sizes, int n_in,
                              void* d_out, int out_size) {
    const float* x   = (const float*)d_in[0];
    const float* z   = (const float*)d_in[1];
    const float* bw  = (const float*)d_in[2];
    const float* dwW = (const float*)d_in[3];
    const float* dwb = (const float*)d_in[4];
    const float* bb  = (const float*)d_in[5];
    const float* dbW = (const float*)d_in[6];
    const float* dbb = (const float*)d_in[7];
    float* out = (float*)d_out;

    // 1) overwrite out with all non-hyper terms
    k_pre<<<dim3(OUT_DIM / 32, BATCH / 32), 256>>>(x, z, bw, dwb, bb, dbW, dbb, out);
    // 2) += hyper-GEMM main term (fp16 tensor cores, pipelined)
    k_main<<<dim3(OUT_DIM / NO_, ISPLIT), 256>>>(x, z, dwW, out);
}